// round 5
// baseline (speedup 1.0000x reference)
#include <cuda_runtime.h>
#include <cuda_bf16.h>
#include <cstdint>

// Problem constants (fixed by the reference).
#define BB 4
#define CC 64
#define TT 8
#define HH 128
#define WW 128
#define DG 8
#define CG 8            // channels per deformable group = CC/DG
#define HW (HH*WW)      // 16384
#define THW (TT*HH*WW)  // 131072

// Channel-last scratch: xT[b][g][t][h][w][c8]  (32 B contiguous per pixel-group)
__device__ float g_xT[(size_t)BB * DG * TT * HH * WW * CG];
// Sampled values for the general-weight path (same layout).
__device__ float g_samp[(size_t)BB * DG * TT * HW * CG];

// Flag: 0 if weight==Identity and bias==0 (fast path), 1 otherwise.
__device__ int g_general;

// Transpose [B,C,T,H,W] -> [B,G,T,H,W,C8]. One block per (b,g,t,h) row.
// Block 0 additionally computes g_general from weight/bias.
__global__ __launch_bounds__(256, 8)
void transpose_kernel(const float* __restrict__ x,
                      const float* __restrict__ wgt,
                      const float* __restrict__ bias) {
    __shared__ float s[CG][WW + 4];
    __shared__ int sbad;

    if (blockIdx.x == 0) {
        if (threadIdx.x == 0) sbad = 0;
        __syncthreads();
        int bad = 0;
        for (int i = threadIdx.x; i < CC * CC; i += 256) {
            float e = ((i >> 6) == (i & 63)) ? 1.0f : 0.0f;
            if (wgt[i] != e) bad = 1;
        }
        if (threadIdx.x < CC && bias[threadIdx.x] != 0.0f) bad = 1;
        if (bad) atomicOr(&sbad, 1);
        __syncthreads();
        if (threadIdx.x == 0) g_general = sbad;
        __syncthreads();
    }

    const int n = blockIdx.x;              // ((b*DG+g)*TT+t)*HH+h
    const int h = n & 127;
    const int t = (n >> 7) & 7;
    const int g = (n >> 10) & 7;
    const int b = n >> 13;

    const int warp = threadIdx.x >> 5;     // channel within group
    const int lane = threadIdx.x & 31;

    const float* src = x + ((size_t)(b * CC + g * CG + warp) * TT + t) * HW
                         + (size_t)h * WW;
    float4 v = ((const float4*)src)[lane];
    s[warp][lane * 4 + 0] = v.x;
    s[warp][lane * 4 + 1] = v.y;
    s[warp][lane * 4 + 2] = v.z;
    s[warp][lane * 4 + 3] = v.w;
    __syncthreads();

    float* dst = g_xT + (size_t)n * (WW * CG);
    const int w  = threadIdx.x >> 1;
    const int c0 = (threadIdx.x & 1) * 4;
    float4 o = make_float4(s[c0 + 0][w], s[c0 + 1][w], s[c0 + 2][w], s[c0 + 3][w]);
    ((float4*)dst)[threadIdx.x] = o;
}

// Gather. 512 threads = 128 pixel-groups (4h x 32w tile) x 4 quarter-threads.
// Quarter q: bit1 = w-corner (w0 / w0+1), bit0 = channel half.
// One warp LDG covers 8 consecutive pixels x the full contiguous 64 B corner
// span [w0..w0+1]x[c0..c7] -> minimal distinct-line visits per instruction.
// Each thread: 4 LDG.128 (one per (t,h) corner). w-corners combined by
// shfl_xor(2); lanes q<2 write the result.
__global__ __launch_bounds__(512, 2)
void deform_kernel(const float* __restrict__ off,
                   float* __restrict__ out) {
    const int n  = blockIdx.x;
    const int wt = n & 3;            // w tile (4)
    const int ht = (n >> 2) & 31;    // h tile (32)
    const int t  = (n >> 7) & 7;
    const int g  = (n >> 10) & 7;
    const int b  = n >> 13;

    const int q    = threadIdx.x & 3;        // quarter of the 64 B span
    const int wq   = q >> 1;                 // w-corner select
    const int half = q & 1;                  // channel half
    const int wl   = (threadIdx.x >> 2) & 31;
    const int hl   = threadIdx.x >> 7;       // 0..3
    const int w    = (wt << 5) + wl;
    const int h    = (ht << 2) + hl;

    // offset layout [B, 3*DG, T, H, W]; channel = g*3 + {0,1,2}
    const int so = ((b * (3 * DG) + g * 3) * TT + t) * HW + h * WW + w;
    const float ot = off[so];
    const float oh = off[so + THW];
    const float ow = off[so + 2 * THW];

    const float gt = (float)t + ot;
    const float gh = (float)h + oh;
    const float gw = (float)w + ow;
    const float ftf = floorf(gt), fhf = floorf(gh), fwf = floorf(gw);
    const int   t0 = (int)ftf,    h0 = (int)fhf,    w0 = (int)fwf;
    const float dt = gt - ftf,    dh = gh - fhf,    dw = gw - fwf;

    // Per-axis weights with validity folded in; clamped indices for
    // unconditional (safe) loads.
    float wta[2], whb[2];
    int   tca[2], hcb[2];
    wta[0] = (1.0f - dt) * (((unsigned)t0       < (unsigned)TT) ? 1.0f : 0.0f);
    wta[1] = dt          * (((unsigned)(t0 + 1) < (unsigned)TT) ? 1.0f : 0.0f);
    whb[0] = (1.0f - dh) * (((unsigned)h0       < (unsigned)HH) ? 1.0f : 0.0f);
    whb[1] = dh          * (((unsigned)(h0 + 1) < (unsigned)HH) ? 1.0f : 0.0f);
    tca[0] = min(TT - 1, max(0, t0));
    tca[1] = min(TT - 1, max(0, t0 + 1));
    hcb[0] = min(HH - 1, max(0, h0));
    hcb[1] = min(HH - 1, max(0, h0 + 1));

    // This thread's w-corner: index, validity-folded weight.
    const int   wcm = w0 + wq;
    const float wwq = (wq ? dw : (1.0f - dw))
                    * (((unsigned)wcm < (unsigned)WW) ? 1.0f : 0.0f);
    const int   wcc = min(WW - 1, max(0, wcm));

    const float* bg = g_xT + (size_t)(b * DG + g) * THW * CG;
    const int    woff = wcc * 2 + half;      // float4 index within a row

    // Batch the 4 independent LDG.128s for MLP.
    float4 u[2][2];
#pragma unroll
    for (int a = 0; a < 2; a++) {
#pragma unroll
        for (int b2 = 0; b2 < 2; b2++) {
            const float4* row =
                (const float4*)(bg + (size_t)(tca[a] * HH + hcb[b2]) * (WW * CG));
            u[a][b2] = __ldg(row + woff);
        }
    }

    float acc0 = 0.f, acc1 = 0.f, acc2 = 0.f, acc3 = 0.f;
#pragma unroll
    for (int a = 0; a < 2; a++) {
#pragma unroll
        for (int b2 = 0; b2 < 2; b2++) {
            const float wc = wta[a] * whb[b2] * wwq;
            acc0 = fmaf(wc, u[a][b2].x, acc0);
            acc1 = fmaf(wc, u[a][b2].y, acc1);
            acc2 = fmaf(wc, u[a][b2].z, acc2);
            acc3 = fmaf(wc, u[a][b2].w, acc3);
        }
    }

    // Combine the two w-corners (lanes q and q^2 hold the same channel half).
    acc0 += __shfl_xor_sync(0xFFFFFFFFu, acc0, 2);
    acc1 += __shfl_xor_sync(0xFFFFFFFFu, acc1, 2);
    acc2 += __shfl_xor_sync(0xFFFFFFFFu, acc2, 2);
    acc3 += __shfl_xor_sync(0xFFFFFFFFu, acc3, 2);

    if (q < 2) {
        if (!g_general) {
            // Identity weight, zero bias: sampled IS the output.
            const size_t ob = ((size_t)(b * CC + g * CG + half * 4) * TT + t) * HW
                            + (size_t)h * WW + w;
            out[ob]           = acc0;
            out[ob + THW]     = acc1;
            out[ob + 2 * THW] = acc2;
            out[ob + 3 * THW] = acc3;
        } else {
            float* dst = g_samp + ((size_t)(b * DG + g) * THW
                         + (size_t)t * HW + (size_t)h * WW + w) * CG + half * 4;
            *((float4*)dst) = make_float4(acc0, acc1, acc2, acc3);
        }
    }
}

// General 1x1x1 conv path (early-exits when weight is identity).
__global__ __launch_bounds__(256, 4)
void conv_kernel(const float* __restrict__ wgt,
                 const float* __restrict__ bias,
                 float* __restrict__ out) {
    if (!g_general) return;
    const int p = blockIdx.x * 256 + threadIdx.x;   // pixel in [0, B*THW)
    const int b = p / THW;
    const int r = p - b * THW;

    float sv[CC];
#pragma unroll
    for (int g = 0; g < DG; g++) {
        const float* src = g_samp + ((size_t)(b * DG + g) * THW + r) * CG;
#pragma unroll
        for (int c = 0; c < CG; c++) sv[g * CG + c] = src[c];
    }
#pragma unroll 4
    for (int o = 0; o < CC; o++) {
        float a = bias[o];
#pragma unroll 16
        for (int c = 0; c < CC; c++)
            a = fmaf(wgt[o * CC + c], sv[c], a);
        out[(size_t)(b * CC + o) * THW + r] = a;
    }
}

extern "C" void kernel_launch(void* const* d_in, const int* in_sizes, int n_in,
                              void* d_out, int out_size) {
    const float* x    = (const float*)d_in[0];
    const float* off  = (const float*)d_in[1];
    const float* wgt  = (const float*)d_in[2];
    const float* bias = (const float*)d_in[3];
    float* out = (float*)d_out;

    const int ntrans = BB * DG * TT * HH;          // 32768
    transpose_kernel<<<ntrans, 256>>>(x, wgt, bias);

    const int nblocks = BB * DG * TT * 32 * 4;     // 32768
    deform_kernel<<<nblocks, 512>>>(off, out);

    conv_kernel<<<(BB * THW) / 256, 256>>>(wgt, bias, out);
}

// round 7
// speedup vs baseline: 1.5410x; 1.5410x over previous
#include <cuda_runtime.h>
#include <cuda_fp16.h>
#include <cstdint>

// Problem constants (fixed by the reference).
#define BB 4
#define CC 64
#define TT 8
#define HH 128
#define WW 128
#define DG 8
#define CG 8            // channels per deformable group = CC/DG
#define HW (HH*WW)      // 16384
#define THW (TT*HH*WW)  // 131072

// Bit-cast helpers (the named intrinsics don't exist in this toolkit).
__device__ __forceinline__ unsigned h2_to_u(__half2 h) {
    union { __half2 h; unsigned u; } c; c.h = h; return c.u;
}
__device__ __forceinline__ __half2 u_to_h2(unsigned u) {
    union { unsigned u; __half2 h; } c; c.u = u; return c.h;
}

// Channel-last fp16 scratch: xT[b][g][t][h][w][c8] (16 B per pixel-group).
__device__ __half g_xT[(size_t)BB * DG * TT * HH * WW * CG];
// Sampled values (fp32) for the general-weight path.
__device__ float g_samp[(size_t)BB * DG * TT * HW * CG];

// Flag: 0 if weight==Identity and bias==0 (fast path), 1 otherwise.
__device__ int g_general;

// Transpose [B,C,T,H,W] fp32 -> [B,G,T,H,W,C8] fp16.
// One block per (b,g,t,h-pair). 256 threads.
__global__ __launch_bounds__(256, 8)
void transpose_kernel(const float* __restrict__ x,
                      const float* __restrict__ wgt,
                      const float* __restrict__ bias) {
    __shared__ float s[2][CG][WW + 4];
    __shared__ int sbad;

    if (blockIdx.x == 0) {
        if (threadIdx.x == 0) sbad = 0;
        __syncthreads();
        int bad = 0;
        for (int i = threadIdx.x; i < CC * CC; i += 256) {
            float e = ((i >> 6) == (i & 63)) ? 1.0f : 0.0f;
            if (wgt[i] != e) bad = 1;
        }
        if (threadIdx.x < CC && bias[threadIdx.x] != 0.0f) bad = 1;
        if (bad) atomicOr(&sbad, 1);
        __syncthreads();
        if (threadIdx.x == 0) g_general = sbad;
        __syncthreads();
    }

    const int n  = blockIdx.x;             // ((b*DG+g)*TT+t)*64 + h2
    const int h2 = n & 63;                 // h pair index
    const int t  = (n >> 6) & 7;
    const int g  = (n >> 9) & 7;
    const int b  = n >> 12;

    const int warp = threadIdx.x >> 5;     // channel within group
    const int lane = threadIdx.x & 31;

    // Read: each warp reads its channel for both rows (float4-coalesced).
#pragma unroll
    for (int r = 0; r < 2; r++) {
        const float* src = x + ((size_t)(b * CC + g * CG + warp) * TT + t) * HW
                             + (size_t)(h2 * 2 + r) * WW;
        float4 v = ((const float4*)src)[lane];
        s[r][warp][lane * 4 + 0] = v.x;
        s[r][warp][lane * 4 + 1] = v.y;
        s[r][warp][lane * 4 + 2] = v.z;
        s[r][warp][lane * 4 + 3] = v.w;
    }
    __syncthreads();

    // Write: thread -> one pixel-group (8 ch fp16 = 16 B).
    const int r = threadIdx.x >> 7;        // row within pair
    const int w = threadIdx.x & 127;
    uint4 o;
    o.x = h2_to_u(__floats2half2_rn(s[r][0][w], s[r][1][w]));
    o.y = h2_to_u(__floats2half2_rn(s[r][2][w], s[r][3][w]));
    o.z = h2_to_u(__floats2half2_rn(s[r][4][w], s[r][5][w]));
    o.w = h2_to_u(__floats2half2_rn(s[r][6][w], s[r][7][w]));
    __half* dst = g_xT + ((size_t)(((b * DG + g) * TT + t) * HH + h2 * 2 + r)) * (WW * CG);
    ((uint4*)dst)[w] = o;
}

// Gather. 256 threads = 128 pixels (4h x 32w tile) x 2 w-corner threads.
// Lane layout: bit0 = w-corner, bits1-5 = w, bits6-7 = h.
// Each thread: 4x LDG.128, each = full 8 fp16 channels of one (t,h) corner.
// shfl_xor(1) combines the two w-corners; even lanes write.
__global__ __launch_bounds__(256, 4)
void deform_kernel(const float* __restrict__ off,
                   float* __restrict__ out) {
    const int n  = blockIdx.x;
    const int wt = n & 3;            // w tile (4)
    const int ht = (n >> 2) & 31;    // h tile (32)
    const int t  = (n >> 7) & 7;
    const int g  = (n >> 10) & 7;
    const int b  = n >> 13;

    const int wq = threadIdx.x & 1;          // w-corner select
    const int wl = (threadIdx.x >> 1) & 31;
    const int hl = threadIdx.x >> 6;         // 0..3
    const int w  = (wt << 5) + wl;
    const int h  = (ht << 2) + hl;

    // offset layout [B, 3*DG, T, H, W]; channel = g*3 + {0,1,2}
    const int so = ((b * (3 * DG) + g * 3) * TT + t) * HW + h * WW + w;
    const float ot = off[so];
    const float oh = off[so + THW];
    const float ow = off[so + 2 * THW];

    const float gt = (float)t + ot;
    const float gh = (float)h + oh;
    const float gw = (float)w + ow;
    const float ftf = floorf(gt), fhf = floorf(gh), fwf = floorf(gw);
    const int   t0 = (int)ftf,    h0 = (int)fhf,    w0 = (int)fwf;
    const float dt = gt - ftf,    dh = gh - fhf,    dw = gw - fwf;

    float wta[2], whb[2];
    int   tca[2], hcb[2];
    wta[0] = (1.0f - dt) * (((unsigned)t0       < (unsigned)TT) ? 1.0f : 0.0f);
    wta[1] = dt          * (((unsigned)(t0 + 1) < (unsigned)TT) ? 1.0f : 0.0f);
    whb[0] = (1.0f - dh) * (((unsigned)h0       < (unsigned)HH) ? 1.0f : 0.0f);
    whb[1] = dh          * (((unsigned)(h0 + 1) < (unsigned)HH) ? 1.0f : 0.0f);
    tca[0] = min(TT - 1, max(0, t0));
    tca[1] = min(TT - 1, max(0, t0 + 1));
    hcb[0] = min(HH - 1, max(0, h0));
    hcb[1] = min(HH - 1, max(0, h0 + 1));

    // This thread's w-corner.
    const int   wcm = w0 + wq;
    const float wwq = (wq ? dw : (1.0f - dw))
                    * (((unsigned)wcm < (unsigned)WW) ? 1.0f : 0.0f);
    const int   wcc = min(WW - 1, max(0, wcm));

    const __half* bg = g_xT + (size_t)(b * DG + g) * THW * CG;

    // Batch the 4 independent 16 B loads (full 8 fp16 channels each).
    uint4 u[2][2];
#pragma unroll
    for (int a = 0; a < 2; a++) {
#pragma unroll
        for (int b2 = 0; b2 < 2; b2++) {
            const uint4* row =
                (const uint4*)(bg + (size_t)(tca[a] * HH + hcb[b2]) * (WW * CG));
            u[a][b2] = __ldg(row + wcc);
        }
    }

    float acc0 = 0.f, acc1 = 0.f, acc2 = 0.f, acc3 = 0.f;
    float acc4 = 0.f, acc5 = 0.f, acc6 = 0.f, acc7 = 0.f;
#pragma unroll
    for (int a = 0; a < 2; a++) {
#pragma unroll
        for (int b2 = 0; b2 < 2; b2++) {
            const float wc = wta[a] * whb[b2] * wwq;
            float2 f0 = __half22float2(u_to_h2(u[a][b2].x));
            float2 f1 = __half22float2(u_to_h2(u[a][b2].y));
            float2 f2 = __half22float2(u_to_h2(u[a][b2].z));
            float2 f3 = __half22float2(u_to_h2(u[a][b2].w));
            acc0 = fmaf(wc, f0.x, acc0); acc1 = fmaf(wc, f0.y, acc1);
            acc2 = fmaf(wc, f1.x, acc2); acc3 = fmaf(wc, f1.y, acc3);
            acc4 = fmaf(wc, f2.x, acc4); acc5 = fmaf(wc, f2.y, acc5);
            acc6 = fmaf(wc, f3.x, acc6); acc7 = fmaf(wc, f3.y, acc7);
        }
    }

    // Combine the two w-corners (lane pairs differ only in bit0).
    acc0 += __shfl_xor_sync(0xFFFFFFFFu, acc0, 1);
    acc1 += __shfl_xor_sync(0xFFFFFFFFu, acc1, 1);
    acc2 += __shfl_xor_sync(0xFFFFFFFFu, acc2, 1);
    acc3 += __shfl_xor_sync(0xFFFFFFFFu, acc3, 1);
    acc4 += __shfl_xor_sync(0xFFFFFFFFu, acc4, 1);
    acc5 += __shfl_xor_sync(0xFFFFFFFFu, acc5, 1);
    acc6 += __shfl_xor_sync(0xFFFFFFFFu, acc6, 1);
    acc7 += __shfl_xor_sync(0xFFFFFFFFu, acc7, 1);

    if (wq == 0) {
        if (!g_general) {
            const size_t ob = ((size_t)(b * CC + g * CG) * TT + t) * HW
                            + (size_t)h * WW + w;
            out[ob]           = acc0;
            out[ob + THW]     = acc1;
            out[ob + 2*THW]   = acc2;
            out[ob + 3*THW]   = acc3;
            out[ob + 4*THW]   = acc4;
            out[ob + 5*THW]   = acc5;
            out[ob + 6*THW]   = acc6;
            out[ob + 7*THW]   = acc7;
        } else {
            float* dst = g_samp + ((size_t)(b * DG + g) * THW
                         + (size_t)t * HW + (size_t)h * WW + w) * CG;
            ((float4*)dst)[0] = make_float4(acc0, acc1, acc2, acc3);
            ((float4*)dst)[1] = make_float4(acc4, acc5, acc6, acc7);
        }
    }
}

// General 1x1x1 conv path (early-exits when weight is identity).
__global__ __launch_bounds__(256, 4)
void conv_kernel(const float* __restrict__ wgt,
                 const float* __restrict__ bias,
                 float* __restrict__ out) {
    if (!g_general) return;
    const int p = blockIdx.x * 256 + threadIdx.x;   // pixel in [0, B*THW)
    const int b = p / THW;
    const int r = p - b * THW;

    float sv[CC];
#pragma unroll
    for (int g = 0; g < DG; g++) {
        const float* src = g_samp + ((size_t)(b * DG + g) * THW + r) * CG;
#pragma unroll
        for (int c = 0; c < CG; c++) sv[g * CG + c] = src[c];
    }
#pragma unroll 4
    for (int o = 0; o < CC; o++) {
        float a = bias[o];
#pragma unroll 16
        for (int c = 0; c < CC; c++)
            a = fmaf(wgt[o * CC + c], sv[c], a);
        out[(size_t)(b * CC + o) * THW + r] = a;
    }
}

extern "C" void kernel_launch(void* const* d_in, const int* in_sizes, int n_in,
                              void* d_out, int out_size) {
    const float* x    = (const float*)d_in[0];
    const float* off  = (const float*)d_in[1];
    const float* wgt  = (const float*)d_in[2];
    const float* bias = (const float*)d_in[3];
    float* out = (float*)d_out;

    const int ntrans = BB * DG * TT * (HH / 2);    // 16384
    transpose_kernel<<<ntrans, 256>>>(x, wgt, bias);

    const int nblocks = BB * DG * TT * 32 * 4;     // 32768
    deform_kernel<<<nblocks, 256>>>(off, out);

    conv_kernel<<<(BB * THW) / 256, 256>>>(wgt, bias, out);
}